// round 2
// baseline (speedup 1.0000x reference)
#include <cuda_runtime.h>
#include <math.h>
#include <float.h>

// Problem constants (shapes fixed by setup_inputs)
#define BB 2048
#define FF 256
#define HH 1024
#define OO 256
#define TT 64

// ---------------- persistent scratch (device globals; no allocation) ----------
__device__ float    g_v [BB*HH];          // hidden membrane
__device__ float    g_i [BB*HH];          // hidden synaptic current
__device__ float    g_vo[BB*OO];          // readout membrane
__device__ float    g_io[BB*OO];          // readout current
__device__ float    g_m [BB*OO];          // running max of vo
__device__ unsigned g_z [2][BB*(HH/32)];  // hidden spikes, bit-packed, ping-pong
__device__ unsigned g_xb[TT*BB*16];       // encoder spikes [t][b][16 words of 32 bits]

// ---------------- init ---------------------------------------------------------
__global__ void init_kernel() {
    int gid = blockIdx.x * 256 + threadIdx.x;
    if (gid < BB*HH) { g_v[gid] = 0.f; g_i[gid] = 0.f; }
    if (gid < BB*OO) { g_vo[gid] = 0.f; g_io[gid] = 0.f; g_m[gid] = -FLT_MAX; }
    if (gid < BB*(HH/32)) g_z[0][gid] = 0u;
}

// ---------------- encoder: constant-current LIF, bit-packed over T -------------
// Exact reference semantics: v = v + 0.1f*((-v) + c), separately rounded (no FMA).
__global__ void enc_kernel(const float* __restrict__ x) {
    int gid = blockIdx.x * 256 + threadIdx.x;   // 0 .. 32767
    int b = gid >> 4;
    int w = gid & 15;
    float sgn = (w < 8) ? 50.f : -50.f;
    int fbase = (w & 7) * 32;
    float c[32], v[32];
#pragma unroll
    for (int j = 0; j < 32; j++) {
        c[j] = fmaxf(__fmul_rn(sgn, x[b*FF + fbase + j]), 0.f);
        v[j] = 0.f;
    }
    unsigned* dst = g_xb + b*16 + w;
    for (int t = 0; t < TT; t++) {
        unsigned msk = 0u;
#pragma unroll
        for (int j = 0; j < 32; j++) {
            float d = __fadd_rn(c[j], -v[j]);                 // (0 - v) + c
            v[j] = __fadd_rn(v[j], __fmul_rn(0.1f, d));       // v + 0.1*(...)
            if (v[j] > 1.0f) { msk |= (1u << j); v[j] = 0.f; }
        }
        dst[t * BB * 16] = msk;
    }
}

// ---------------- one K-chunk of the spike GEMM --------------------------------
// Stages a 64x32 weight tile (transposed) and a 64-row spike bit-word expanded
// to fp32, then runs the 4x4 register FMA micro-tile. Ascending-K FMA chain.
__device__ __forceinline__ void do_chunk(
        const float* __restrict__ wbase, int rowlen, int n0, int koff,
        const unsigned* __restrict__ zw, int zstride,
        float (*aT)[68], float (*wT)[68],
        int tid, int tidx, int tidy, float acc[4][4]) {
#pragma unroll
    for (int q = 0; q < 2; q++) {
        int idx = tid + q * 256;
        int hr  = idx >> 3;
        int j4  = idx & 7;
        float4 wv = *(const float4*)&wbase[(n0 + hr) * rowlen + koff + j4 * 4];
        wT[j4*4 + 0][hr] = wv.x;
        wT[j4*4 + 1][hr] = wv.y;
        wT[j4*4 + 2][hr] = wv.z;
        wT[j4*4 + 3][hr] = wv.w;
    }
    {
        int r = tid & 63;
        int quarter = tid >> 6;
        unsigned word = zw[r * zstride];
#pragma unroll
        for (int jj = 0; jj < 8; jj++) {
            int j = quarter * 8 + jj;
            aT[j][r] = ((word >> j) & 1u) ? 1.0f : 0.0f;
        }
    }
    __syncthreads();
#pragma unroll
    for (int j = 0; j < 32; j++) {
        float4 a4 = *(const float4*)&aT[j][tidy * 4];
        float4 w4 = *(const float4*)&wT[j][tidx * 4];
        float av[4]  = {a4.x, a4.y, a4.z, a4.w};
        float wv4[4] = {w4.x, w4.y, w4.z, w4.w};
#pragma unroll
        for (int u = 0; u < 4; u++)
#pragma unroll
            for (int c = 0; c < 4; c++)
                acc[u][c] = __fmaf_rn(av[u], wv4[c], acc[u][c]);
    }
    __syncthreads();
}

// ---------------- fused per-step kernel ----------------------------------------
// Launch s (0..TT):
//   role A (blockIdx < 512): hidden update for step s   (reads z_{s-1} = g_z[s&1],
//                             writes z_s = g_z[(s+1)&1]); skipped at s==TT.
//   role B (blockIdx >= 512): readout update for step s-1; skipped at s==0.
__global__ __launch_bounds__(256) void step_kernel(
        int s,
        const float* __restrict__ w_in,
        const float* __restrict__ w_rec,
        const float* __restrict__ w_out) {
    __shared__ float    aT[32][68];
    __shared__ float    wT[32][68];
    __shared__ unsigned zsh[64][2];

    const int tid  = threadIdx.x;
    const int tidx = tid & 15;         // n (h or o) group
    const int tidy = tid >> 4;         // b group
    const bool roleA = (blockIdx.x < 512);
    if (roleA && s >= TT) return;
    if (!roleA && s == 0) return;
    const int pr = s & 1;              // buffer holding z_{s-1}

    if (roleA) {
        const int b0 = (blockIdx.x >> 4) * 64;
        const int n0 = (blockIdx.x & 15) * 64;

        float accIn[4][4], accRec[4][4];
#pragma unroll
        for (int u = 0; u < 4; u++)
#pragma unroll
            for (int c = 0; c < 4; c++) { accIn[u][c] = 0.f; accRec[u][c] = 0.f; }

        // input matmul: xt @ w_in.T   (K = 512, encoder spike words)
        for (int ch = 0; ch < 16; ch++)
            do_chunk(w_in, 512, n0, ch * 32,
                     &g_xb[(s * BB + b0) * 16 + ch], 16,
                     aT, wT, tid, tidx, tidy, accIn);
        // recurrent matmul: z @ w_rec.T (K = 1024, hidden spike words)
        for (int ch = 0; ch < 32; ch++)
            do_chunk(w_rec, 1024, n0, ch * 32,
                     &g_z[pr][b0 * 32 + ch], 32,
                     aT, wT, tid, tidx, tidy, accRec);

        // -------- hidden neuron update + spike bit production --------
        if (tid < 128) zsh[tid >> 1][tid & 1] = 0u;
        __syncthreads();
        const int hc   = n0 + tidx * 4;
        const int wsel = tidx >> 3;
        const int shf  = (tidx & 7) * 4;
#pragma unroll
        for (int u = 0; u < 4; u++) {
            int b = b0 + tidy * 4 + u;
            int base = b * HH + hc;
            float4 i4 = *(const float4*)&g_i[base];
            float4 v4 = *(const float4*)&g_v[base];
            float ia[4] = {i4.x, i4.y, i4.z, i4.w};
            float va[4] = {v4.x, v4.y, v4.z, v4.w};
            unsigned nib = 0u;
#pragma unroll
            for (int c = 0; c < 4; c++) {
                // v_dec = v + 0.1*((-v) + i), separately rounded
                float d   = __fadd_rn(ia[c], -va[c]);
                float vd  = __fadd_rn(va[c], __fmul_rn(0.1f, d));
                // i_dec = i - 0.2*i
                float idc = __fsub_rn(ia[c], __fmul_rn(0.2f, ia[c]));
                bool  z   = vd > 1.0f;
                va[c] = z ? 0.0f : vd;
                // i_new = (i_dec + accIn) + accRec  (reference op order)
                ia[c] = __fadd_rn(__fadd_rn(idc, accIn[u][c]), accRec[u][c]);
                if (z) nib |= (1u << c);
            }
            *(float4*)&g_v[base] = make_float4(va[0], va[1], va[2], va[3]);
            *(float4*)&g_i[base] = make_float4(ia[0], ia[1], ia[2], ia[3]);
            if (nib) atomicOr(&zsh[tidy * 4 + u][wsel], nib << shf);
        }
        __syncthreads();
        if (tid < 128) {
            int r = tid >> 1, w2 = tid & 1;
            g_z[pr ^ 1][(b0 + r) * 32 + (n0 >> 5) + w2] = zsh[r][w2];
        }
    } else {
        const int id = blockIdx.x - 512;
        const int b0 = (id >> 2) * 64;
        const int n0 = (id & 3) * 64;

        float acc[4][4];
#pragma unroll
        for (int u = 0; u < 4; u++)
#pragma unroll
            for (int c = 0; c < 4; c++) acc[u][c] = 0.f;

        // readout matmul: z_new @ w_out.T (K = 1024)
        for (int ch = 0; ch < 32; ch++)
            do_chunk(w_out, 1024, n0, ch * 32,
                     &g_z[pr][b0 * 32 + ch], 32,
                     aT, wT, tid, tidx, tidy, acc);

        // -------- LI readout update + running max --------
        const int oc = n0 + tidx * 4;
#pragma unroll
        for (int u = 0; u < 4; u++) {
            int b = b0 + tidy * 4 + u;
            int base = b * OO + oc;
            float4 io4 = *(const float4*)&g_io[base];
            float4 vo4 = *(const float4*)&g_vo[base];
            float4 m4  = *(const float4*)&g_m[base];
            float ioa[4] = {io4.x, io4.y, io4.z, io4.w};
            float voa[4] = {vo4.x, vo4.y, vo4.z, vo4.w};
            float ma[4]  = {m4.x,  m4.y,  m4.z,  m4.w};
#pragma unroll
            for (int c = 0; c < 4; c++) {
                // vo_new = vo + 0.1*((-vo) + io), separately rounded (old io)
                float d   = __fadd_rn(ioa[c], -voa[c]);
                float von = __fadd_rn(voa[c], __fmul_rn(0.1f, d));
                // io_new = (io - 0.2*io) + acc
                float idc = __fsub_rn(ioa[c], __fmul_rn(0.2f, ioa[c]));
                float ion = __fadd_rn(idc, acc[u][c]);
                ma[c]  = fmaxf(ma[c], von);
                voa[c] = von; ioa[c] = ion;
            }
            *(float4*)&g_vo[base] = make_float4(voa[0], voa[1], voa[2], voa[3]);
            *(float4*)&g_io[base] = make_float4(ioa[0], ioa[1], ioa[2], ioa[3]);
            *(float4*)&g_m[base]  = make_float4(ma[0],  ma[1],  ma[2],  ma[3]);
        }
    }
}

// ---------------- softmax over O=256 per batch row -----------------------------
__global__ void softmax_kernel(float* __restrict__ out) {
    __shared__ float red[256];
    int b = blockIdx.x, o = threadIdx.x;
    float v = g_m[b * OO + o];
    red[o] = v; __syncthreads();
    for (int st = 128; st > 0; st >>= 1) {
        if (o < st) red[o] = fmaxf(red[o], red[o + st]);
        __syncthreads();
    }
    float mx = red[0]; __syncthreads();
    float e = expf(__fsub_rn(v, mx));
    red[o] = e; __syncthreads();
    for (int st = 128; st > 0; st >>= 1) {
        if (o < st) red[o] += red[o + st];
        __syncthreads();
    }
    out[b * OO + o] = e / red[0];
}

// ---------------- launcher ------------------------------------------------------
extern "C" void kernel_launch(void* const* d_in, const int* in_sizes, int n_in,
                              void* d_out, int out_size) {
    const float* x     = (const float*)d_in[0];
    const float* w_in  = (const float*)d_in[1];
    const float* w_rec = (const float*)d_in[2];
    const float* w_out = (const float*)d_in[3];
    float* out = (float*)d_out;

    init_kernel<<<(BB * HH + 255) / 256, 256>>>();
    enc_kernel<<<BB * 16 / 256, 256>>>(x);
    // launch s: role A does hidden step s, role B does readout step s-1.
    for (int s = 0; s <= TT; s++)
        step_kernel<<<640, 256>>>(s, w_in, w_rec, w_out);
    softmax_kernel<<<BB, 256>>>(out);
}

// round 3
// speedup vs baseline: 1.0041x; 1.0041x over previous
#include <cuda_runtime.h>
#include <math.h>
#include <float.h>

// Problem constants (shapes fixed by setup_inputs)
#define BB 2048
#define FF 256
#define HH 1024
#define OO 256
#define TT 64

// ---------------- persistent scratch (device globals; no allocation) ----------
__device__ float    g_v [BB*HH];          // hidden membrane
__device__ float    g_i [BB*HH];          // hidden synaptic current
__device__ float    g_vo[BB*OO];          // readout membrane
__device__ float    g_io[BB*OO];          // readout current
__device__ float    g_m [BB*OO];          // running max of vo
__device__ unsigned g_z [2][BB*(HH/32)];  // hidden spikes, bit-packed, ping-pong
__device__ unsigned g_xb[TT*BB*16];       // encoder spikes [t][b][16 words of 32 bits]

// ---------------- init ---------------------------------------------------------
__global__ void init_kernel() {
    int gid = blockIdx.x * 256 + threadIdx.x;
    if (gid < BB*HH) { g_v[gid] = 0.f; g_i[gid] = 0.f; }
    if (gid < BB*OO) { g_vo[gid] = 0.f; g_io[gid] = 0.f; g_m[gid] = -FLT_MAX; }
    if (gid < BB*(HH/32)) g_z[0][gid] = 0u;
}

// ---------------- encoder: constant-current LIF, bit-packed over T -------------
// Exact reference semantics: v = v + 0.1f*((-v) + c), separately rounded (no FMA).
__global__ void enc_kernel(const float* __restrict__ x) {
    int gid = blockIdx.x * 256 + threadIdx.x;   // 0 .. 32767
    int b = gid >> 4;
    int w = gid & 15;
    float sgn = (w < 8) ? 50.f : -50.f;
    int fbase = (w & 7) * 32;
    float c[32], v[32];
#pragma unroll
    for (int j = 0; j < 32; j++) {
        c[j] = fmaxf(__fmul_rn(sgn, x[b*FF + fbase + j]), 0.f);
        v[j] = 0.f;
    }
    unsigned* dst = g_xb + b*16 + w;
    for (int t = 0; t < TT; t++) {
        unsigned msk = 0u;
#pragma unroll
        for (int j = 0; j < 32; j++) {
            float d = __fadd_rn(c[j], -v[j]);                 // (0 - v) + c
            v[j] = __fadd_rn(v[j], __fmul_rn(0.1f, d));       // v + 0.1*(...)
            if (v[j] > 1.0f) { msk |= (1u << j); v[j] = 0.f; }
        }
        dst[t * BB * 16] = msk;
    }
}

// ---------------- one K-chunk of the spike GEMM --------------------------------
// Stages a 64x32 weight tile (transposed) and a 64-row spike bit-word expanded
// to fp32, then runs the 4x4 register FMA micro-tile. Ascending-K FMA chain.
__device__ __forceinline__ void do_chunk(
        const float* __restrict__ wbase, int rowlen, int n0, int koff,
        const unsigned* __restrict__ zw, int zstride,
        float (*aT)[68], float (*wT)[68],
        int tid, int tidx, int tidy, float acc[4][4]) {
#pragma unroll
    for (int q = 0; q < 2; q++) {
        int idx = tid + q * 256;
        int hr  = idx >> 3;
        int j4  = idx & 7;
        float4 wv = *(const float4*)&wbase[(n0 + hr) * rowlen + koff + j4 * 4];
        wT[j4*4 + 0][hr] = wv.x;
        wT[j4*4 + 1][hr] = wv.y;
        wT[j4*4 + 2][hr] = wv.z;
        wT[j4*4 + 3][hr] = wv.w;
    }
    {
        int r = tid & 63;
        int quarter = tid >> 6;
        unsigned word = zw[r * zstride];
#pragma unroll
        for (int jj = 0; jj < 8; jj++) {
            int j = quarter * 8 + jj;
            aT[j][r] = ((word >> j) & 1u) ? 1.0f : 0.0f;
        }
    }
    __syncthreads();
#pragma unroll
    for (int j = 0; j < 32; j++) {
        float4 a4 = *(const float4*)&aT[j][tidy * 4];
        float4 w4 = *(const float4*)&wT[j][tidx * 4];
        float av[4]  = {a4.x, a4.y, a4.z, a4.w};
        float wv4[4] = {w4.x, w4.y, w4.z, w4.w};
#pragma unroll
        for (int u = 0; u < 4; u++)
#pragma unroll
            for (int c = 0; c < 4; c++)
                acc[u][c] = __fmaf_rn(av[u], wv4[c], acc[u][c]);
    }
    __syncthreads();
}

// ---------------- fused per-step kernel ----------------------------------------
// Launch s (0..TT):
//   role A (blockIdx < 512): hidden update for step s   (reads z_{s-1} = g_z[s&1],
//                             writes z_s = g_z[(s+1)&1]); skipped at s==TT.
//   role B (blockIdx >= 512): readout update for step s-1; skipped at s==0.
__global__ __launch_bounds__(256) void step_kernel(
        int s,
        const float* __restrict__ w_in,
        const float* __restrict__ w_rec,
        const float* __restrict__ w_out) {
    __shared__ float    aT[32][68];
    __shared__ float    wT[32][68];
    __shared__ unsigned zsh[64][2];

    const int tid  = threadIdx.x;
    const int tidx = tid & 15;         // n (h or o) group
    const int tidy = tid >> 4;         // b group
    const bool roleA = (blockIdx.x < 512);
    if (roleA && s >= TT) return;
    if (!roleA && s == 0) return;
    const int pr = s & 1;              // buffer holding z_{s-1}

    if (roleA) {
        const int b0 = (blockIdx.x >> 4) * 64;
        const int n0 = (blockIdx.x & 15) * 64;

        float accIn[4][4], accRec[4][4];
#pragma unroll
        for (int u = 0; u < 4; u++)
#pragma unroll
            for (int c = 0; c < 4; c++) { accIn[u][c] = 0.f; accRec[u][c] = 0.f; }

        // input matmul: xt @ w_in.T   (K = 512, encoder spike words)
        for (int ch = 0; ch < 16; ch++)
            do_chunk(w_in, 512, n0, ch * 32,
                     &g_xb[(s * BB + b0) * 16 + ch], 16,
                     aT, wT, tid, tidx, tidy, accIn);
        // recurrent matmul: z @ w_rec.T (K = 1024, hidden spike words)
        for (int ch = 0; ch < 32; ch++)
            do_chunk(w_rec, 1024, n0, ch * 32,
                     &g_z[pr][b0 * 32 + ch], 32,
                     aT, wT, tid, tidx, tidy, accRec);

        // -------- hidden neuron update + spike bit production --------
        if (tid < 128) zsh[tid >> 1][tid & 1] = 0u;
        __syncthreads();
        const int hc   = n0 + tidx * 4;
        const int wsel = tidx >> 3;
        const int shf  = (tidx & 7) * 4;
#pragma unroll
        for (int u = 0; u < 4; u++) {
            int b = b0 + tidy * 4 + u;
            int base = b * HH + hc;
            float4 i4 = *(const float4*)&g_i[base];
            float4 v4 = *(const float4*)&g_v[base];
            float ia[4] = {i4.x, i4.y, i4.z, i4.w};
            float va[4] = {v4.x, v4.y, v4.z, v4.w};
            unsigned nib = 0u;
#pragma unroll
            for (int c = 0; c < 4; c++) {
                // v_dec = v + 0.1*((-v) + i), separately rounded
                float d   = __fadd_rn(ia[c], -va[c]);
                float vd  = __fadd_rn(va[c], __fmul_rn(0.1f, d));
                // i_dec = i - 0.2*i
                float idc = __fsub_rn(ia[c], __fmul_rn(0.2f, ia[c]));
                bool  z   = vd > 1.0f;
                va[c] = z ? 0.0f : vd;
                // i_new = (i_dec + accIn) + accRec  (reference op order)
                ia[c] = __fadd_rn(__fadd_rn(idc, accIn[u][c]), accRec[u][c]);
                if (z) nib |= (1u << c);
            }
            *(float4*)&g_v[base] = make_float4(va[0], va[1], va[2], va[3]);
            *(float4*)&g_i[base] = make_float4(ia[0], ia[1], ia[2], ia[3]);
            if (nib) atomicOr(&zsh[tidy * 4 + u][wsel], nib << shf);
        }
        __syncthreads();
        if (tid < 128) {
            int r = tid >> 1, w2 = tid & 1;
            g_z[pr ^ 1][(b0 + r) * 32 + (n0 >> 5) + w2] = zsh[r][w2];
        }
    } else {
        const int id = blockIdx.x - 512;
        const int b0 = (id >> 2) * 64;
        const int n0 = (id & 3) * 64;

        float acc[4][4];
#pragma unroll
        for (int u = 0; u < 4; u++)
#pragma unroll
            for (int c = 0; c < 4; c++) acc[u][c] = 0.f;

        // readout matmul: z_new @ w_out.T (K = 1024)
        for (int ch = 0; ch < 32; ch++)
            do_chunk(w_out, 1024, n0, ch * 32,
                     &g_z[pr][b0 * 32 + ch], 32,
                     aT, wT, tid, tidx, tidy, acc);

        // -------- LI readout update + running max --------
        const int oc = n0 + tidx * 4;
#pragma unroll
        for (int u = 0; u < 4; u++) {
            int b = b0 + tidy * 4 + u;
            int base = b * OO + oc;
            float4 io4 = *(const float4*)&g_io[base];
            float4 vo4 = *(const float4*)&g_vo[base];
            float4 m4  = *(const float4*)&g_m[base];
            float ioa[4] = {io4.x, io4.y, io4.z, io4.w};
            float voa[4] = {vo4.x, vo4.y, vo4.z, vo4.w};
            float ma[4]  = {m4.x,  m4.y,  m4.z,  m4.w};
#pragma unroll
            for (int c = 0; c < 4; c++) {
                // vo_new = vo + 0.1*((-vo) + io), separately rounded (old io)
                float d   = __fadd_rn(ioa[c], -voa[c]);
                float von = __fadd_rn(voa[c], __fmul_rn(0.1f, d));
                // io_new = (io - 0.2*io) + acc
                float idc = __fsub_rn(ioa[c], __fmul_rn(0.2f, ioa[c]));
                float ion = __fadd_rn(idc, acc[u][c]);
                ma[c]  = fmaxf(ma[c], von);
                voa[c] = von; ioa[c] = ion;
            }
            *(float4*)&g_vo[base] = make_float4(voa[0], voa[1], voa[2], voa[3]);
            *(float4*)&g_io[base] = make_float4(ioa[0], ioa[1], ioa[2], ioa[3]);
            *(float4*)&g_m[base]  = make_float4(ma[0],  ma[1],  ma[2],  ma[3]);
        }
    }
}

// ---------------- softmax over O=256 per batch row -----------------------------
__global__ void softmax_kernel(float* __restrict__ out) {
    __shared__ float red[256];
    int b = blockIdx.x, o = threadIdx.x;
    float v = g_m[b * OO + o];
    red[o] = v; __syncthreads();
    for (int st = 128; st > 0; st >>= 1) {
        if (o < st) red[o] = fmaxf(red[o], red[o + st]);
        __syncthreads();
    }
    float mx = red[0]; __syncthreads();
    float e = expf(__fsub_rn(v, mx));
    red[o] = e; __syncthreads();
    for (int st = 128; st > 0; st >>= 1) {
        if (o < st) red[o] += red[o + st];
        __syncthreads();
    }
    out[b * OO + o] = e / red[0];
}

// ---------------- launcher ------------------------------------------------------
extern "C" void kernel_launch(void* const* d_in, const int* in_sizes, int n_in,
                              void* d_out, int out_size) {
    const float* x     = (const float*)d_in[0];
    const float* w_in  = (const float*)d_in[1];
    const float* w_rec = (const float*)d_in[2];
    const float* w_out = (const float*)d_in[3];
    float* out = (float*)d_out;

    init_kernel<<<(BB * HH + 255) / 256, 256>>>();
    enc_kernel<<<BB * 16 / 256, 256>>>(x);
    // launch s: role A does hidden step s, role B does readout step s-1.
    for (int s = 0; s <= TT; s++)
        step_kernel<<<640, 256>>>(s, w_in, w_rec, w_out);
    softmax_kernel<<<BB, 256>>>(out);
}